// round 1
// baseline (speedup 1.0000x reference)
#include <cuda_runtime.h>

// Polar decomposition of A = rotation[n] @ mat via det-scaled Newton iteration:
//   X_{k+1} = 0.5 * (g*X + cof(X) / (g * det(X))),  g = |det X|^{-1/3}
// converges to the orthogonal polar factor Q = U @ V^T of the SVD.
// logdet output is identically zero per the reference.

#define TPB 256

__global__ void __launch_bounds__(TPB)
polar_kernel(const float* __restrict__ rot,
             const float* __restrict__ mat,
             float* __restrict__ out,
             float* __restrict__ logdet,
             int N)
{
    __shared__ float s[TPB * 9];
    const int tid  = threadIdx.x;
    const int base = blockIdx.x * TPB;
    const int nmat = min(TPB, N - base);
    const int nflt = nmat * 9;

    // ---- cooperative vectorized load: global (coalesced float4) -> smem ----
    {
        const float* g = rot + (size_t)base * 9;
        const int nv = nflt >> 2;                       // float4 count
        const float4* g4 = reinterpret_cast<const float4*>(g);
        float4* s4 = reinterpret_cast<float4*>(s);
        for (int i = tid; i < nv; i += TPB) s4[i] = g4[i];
        for (int i = (nv << 2) + tid; i < nflt; i += TPB) s[i] = g[i];
    }

    // broadcast 3x3 learned matrix
    const float m0 = __ldg(mat + 0), m1 = __ldg(mat + 1), m2 = __ldg(mat + 2);
    const float m3 = __ldg(mat + 3), m4 = __ldg(mat + 4), m5 = __ldg(mat + 5);
    const float m6 = __ldg(mat + 6), m7 = __ldg(mat + 7), m8 = __ldg(mat + 8);
    __syncthreads();

    const bool active = (tid < nmat);

    // X = R @ M  (inactive threads get identity so they never block the warp vote)
    float x0 = 1.f, x1 = 0.f, x2 = 0.f;
    float x3 = 0.f, x4 = 1.f, x5 = 0.f;
    float x6 = 0.f, x7 = 0.f, x8 = 1.f;
    if (active) {
        const float r0 = s[tid * 9 + 0], r1 = s[tid * 9 + 1], r2 = s[tid * 9 + 2];
        const float r3 = s[tid * 9 + 3], r4 = s[tid * 9 + 4], r5 = s[tid * 9 + 5];
        const float r6 = s[tid * 9 + 6], r7 = s[tid * 9 + 7], r8 = s[tid * 9 + 8];
        x0 = r0 * m0 + r1 * m3 + r2 * m6;
        x1 = r0 * m1 + r1 * m4 + r2 * m7;
        x2 = r0 * m2 + r1 * m5 + r2 * m8;
        x3 = r3 * m0 + r4 * m3 + r5 * m6;
        x4 = r3 * m1 + r4 * m4 + r5 * m7;
        x5 = r3 * m2 + r4 * m5 + r5 * m8;
        x6 = r6 * m0 + r7 * m3 + r8 * m6;
        x7 = r6 * m1 + r7 * m4 + r8 * m7;
        x8 = r6 * m2 + r7 * m5 + r8 * m8;
    }

    // ---- det-scaled Newton iteration to the polar factor ----
    #pragma unroll 1
    for (int it = 0; it < 12; ++it) {
        // cofactor matrix (so that X^{-T} = cof(X) / det(X))
        const float c00 = x4 * x8 - x5 * x7;
        const float c01 = x5 * x6 - x3 * x8;
        const float c02 = x3 * x7 - x4 * x6;
        const float c10 = x2 * x7 - x1 * x8;
        const float c11 = x0 * x8 - x2 * x6;
        const float c12 = x1 * x6 - x0 * x7;
        const float c20 = x1 * x5 - x2 * x4;
        const float c21 = x2 * x3 - x0 * x5;
        const float c22 = x0 * x4 - x1 * x3;
        const float det = x0 * c00 + x1 * c01 + x2 * c02;

        const float ad = fmaxf(fabsf(det), 1e-36f);
        const float g  = exp2f(-0.33333333f * __log2f(ad));   // |det|^{-1/3}
        const float r  = 0.5f * __frcp_rn(g * det);           // 0.5 / det(g*X)... * g^2 folded
        const float hg = 0.5f * g;

        x0 = hg * x0 + r * c00;
        x1 = hg * x1 + r * c01;
        x2 = hg * x2 + r * c02;
        x3 = hg * x3 + r * c10;
        x4 = hg * x4 + r * c11;
        x5 = hg * x5 + r * c12;
        x6 = hg * x6 + r * c20;
        x7 = hg * x7 + r * c21;
        x8 = hg * x8 + r * c22;

        // convergence: ||X||_F^2 -> 3 (all singular values -> 1)
        const float fro = x0 * x0 + x1 * x1 + x2 * x2
                        + x3 * x3 + x4 * x4 + x5 * x5
                        + x6 * x6 + x7 * x7 + x8 * x8;
        if (__all_sync(0xffffffffu, fabsf(fro - 3.0f) < 2e-5f)) break;
    }

    // ---- stage result to smem, cooperative vectorized store ----
    if (active) {
        s[tid * 9 + 0] = x0; s[tid * 9 + 1] = x1; s[tid * 9 + 2] = x2;
        s[tid * 9 + 3] = x3; s[tid * 9 + 4] = x4; s[tid * 9 + 5] = x5;
        s[tid * 9 + 6] = x6; s[tid * 9 + 7] = x7; s[tid * 9 + 8] = x8;
    }
    __syncthreads();
    {
        float* g = out + (size_t)base * 9;
        const int nv = nflt >> 2;
        const float4* s4 = reinterpret_cast<const float4*>(s);
        float4* g4 = reinterpret_cast<float4*>(g);
        for (int i = tid; i < nv; i += TPB) g4[i] = s4[i];
        for (int i = (nv << 2) + tid; i < nflt; i += TPB) g[i] = s[i];
    }

    const int gid = base + tid;
    if (gid < N) logdet[gid] = 0.0f;
}

__global__ void zero_tail_kernel(float* __restrict__ p, long long n)
{
    long long i = (long long)blockIdx.x * blockDim.x + threadIdx.x;
    if (i < n) p[i] = 0.0f;
}

extern "C" void kernel_launch(void* const* d_in, const int* in_sizes, int n_in,
                              void* d_out, int out_size)
{
    const float* rot = (const float*)d_in[0];
    const float* mat = (const float*)d_in[1];
    float* out = (float*)d_out;

    const int N = in_sizes[0] / 9;
    float* logdet = out + (size_t)N * 9;

    const int blocks = (N + TPB - 1) / TPB;
    polar_kernel<<<blocks, TPB>>>(rot, mat, out, logdet, N);

    // Defensive: zero any output elements beyond out[9N] + logdet[N]
    const long long used = 10LL * N;
    if ((long long)out_size > used) {
        const long long extra = (long long)out_size - used;
        const int zb = (int)((extra + 255) / 256);
        zero_tail_kernel<<<zb, 256>>>(out + used, extra);
    }
}

// round 2
// speedup vs baseline: 1.2387x; 1.2387x over previous
#include <cuda_runtime.h>

// Polar decomposition of A = rotation[n] @ mat, 2 matrices per thread packed
// into f32x2 (Blackwell FFMA2), det-scaled Newton iteration:
//   X <- 0.5*(g*X + cof(X)/(g*det X)),  g = |det X|^(-1/3)

#define TPB 256
typedef unsigned long long u64;

__device__ __forceinline__ u64 f2pack(float lo, float hi) {
    u64 r; asm("mov.b64 %0, {%1, %2};" : "=l"(r) : "f"(lo), "f"(hi)); return r;
}
__device__ __forceinline__ void f2unpack(u64 v, float& lo, float& hi) {
    asm("mov.b64 {%0, %1}, %2;" : "=f"(lo), "=f"(hi) : "l"(v));
}
__device__ __forceinline__ u64 f2mul(u64 a, u64 b) {
    u64 d; asm("mul.rn.f32x2 %0, %1, %2;" : "=l"(d) : "l"(a), "l"(b)); return d;
}
__device__ __forceinline__ u64 f2fma(u64 a, u64 b, u64 c) {
    u64 d; asm("fma.rn.f32x2 %0, %1, %2, %3;" : "=l"(d) : "l"(a), "l"(b), "l"(c)); return d;
}
__device__ __forceinline__ u64 f2neg(u64 a) { return a ^ 0x8000000080000000ULL; }
// a*b - c*d  (packed)
__device__ __forceinline__ u64 f2msub(u64 a, u64 b, u64 c, u64 d) {
    return f2fma(a, b, f2neg(f2mul(c, d)));
}
__device__ __forceinline__ float frcp_fast(float x) {
    float r; asm("rcp.approx.f32 %0, %1;" : "=f"(r) : "f"(x)); return r;
}

__global__ void __launch_bounds__(TPB)
polar2_kernel(const float* __restrict__ rot,
              const float* __restrict__ mat,
              float* __restrict__ out,
              float* __restrict__ logdet,
              int N)
{
    __shared__ float s[TPB * 18];
    const int tid  = threadIdx.x;
    const int base = blockIdx.x * (TPB * 2);          // first matrix of block
    const int nmat = min(TPB * 2, N - base);
    const int nflt = nmat * 9;

    // ---- cooperative vectorized load: global -> smem ----
    {
        const float* g = rot + (size_t)base * 9;
        const int nv = nflt >> 2;
        const float4* g4 = reinterpret_cast<const float4*>(g);
        float4* s4 = reinterpret_cast<float4*>(s);
        for (int i = tid; i < nv; i += TPB) s4[i] = g4[i];
        for (int i = (nv << 2) + tid; i < nflt; i += TPB) s[i] = g[i];
    }

    const float m0 = __ldg(mat + 0), m1 = __ldg(mat + 1), m2 = __ldg(mat + 2);
    const float m3 = __ldg(mat + 3), m4 = __ldg(mat + 4), m5 = __ldg(mat + 5);
    const float m6 = __ldg(mat + 6), m7 = __ldg(mat + 7), m8 = __ldg(mat + 8);
    __syncthreads();

    const bool vlo = (base + 2 * tid)     < N;
    const bool vhi = (base + 2 * tid + 1) < N;

    // gather two matrices into packed registers (identity for invalid slots)
    u64 R[9];
    {
        const int olo = 2 * tid * 9, ohi = olo + 9;
        #pragma unroll
        for (int k = 0; k < 9; ++k) {
            const float idv = (k == 0 || k == 4 || k == 8) ? 1.0f : 0.0f;
            const float a = vlo ? s[olo + k] : idv;
            const float b = vhi ? s[ohi + k] : idv;
            R[k] = f2pack(a, b);
        }
    }
    __syncthreads();   // smem reused for the store stage

    // X = R @ M (packed; M broadcast into both lanes)
    const u64 M0 = f2pack(m0, m0), M1 = f2pack(m1, m1), M2 = f2pack(m2, m2);
    const u64 M3 = f2pack(m3, m3), M4 = f2pack(m4, m4), M5 = f2pack(m5, m5);
    const u64 M6 = f2pack(m6, m6), M7 = f2pack(m7, m7), M8 = f2pack(m8, m8);

    u64 x0 = f2fma(R[0], M0, f2fma(R[1], M3, f2mul(R[2], M6)));
    u64 x1 = f2fma(R[0], M1, f2fma(R[1], M4, f2mul(R[2], M7)));
    u64 x2 = f2fma(R[0], M2, f2fma(R[1], M5, f2mul(R[2], M8)));
    u64 x3 = f2fma(R[3], M0, f2fma(R[4], M3, f2mul(R[5], M6)));
    u64 x4 = f2fma(R[3], M1, f2fma(R[4], M4, f2mul(R[5], M7)));
    u64 x5 = f2fma(R[3], M2, f2fma(R[4], M5, f2mul(R[5], M8)));
    u64 x6 = f2fma(R[6], M0, f2fma(R[7], M3, f2mul(R[8], M6)));
    u64 x7 = f2fma(R[6], M1, f2fma(R[7], M4, f2mul(R[8], M7)));
    u64 x8 = f2fma(R[6], M2, f2fma(R[7], M5, f2mul(R[8], M8)));

    // ---- det-scaled Newton iteration (packed over 2 matrices) ----
    #pragma unroll 1
    for (int it = 0; it < 12; ++it) {
        const u64 c00 = f2msub(x4, x8, x5, x7);
        const u64 c01 = f2msub(x5, x6, x3, x8);
        const u64 c02 = f2msub(x3, x7, x4, x6);
        const u64 c10 = f2msub(x2, x7, x1, x8);
        const u64 c11 = f2msub(x0, x8, x2, x6);
        const u64 c12 = f2msub(x1, x6, x0, x7);
        const u64 c20 = f2msub(x1, x5, x2, x4);
        const u64 c21 = f2msub(x2, x3, x0, x5);
        const u64 c22 = f2msub(x0, x4, x1, x3);
        const u64 det = f2fma(x0, c00, f2fma(x1, c01, f2mul(x2, c02)));

        float dl, dh;
        f2unpack(det, dl, dh);
        const float adl = fmaxf(fabsf(dl), 1e-36f);
        const float adh = fmaxf(fabsf(dh), 1e-36f);
        const float gl = exp2f(-0.33333333f * __log2f(adl));   // |det|^(-1/3)
        const float gh = exp2f(-0.33333333f * __log2f(adh));
        const float rl = 0.5f * frcp_fast(gl * dl);
        const float rh = 0.5f * frcp_fast(gh * dh);
        const u64 hg = f2pack(0.5f * gl, 0.5f * gh);
        const u64 rr = f2pack(rl, rh);

        x0 = f2fma(rr, c00, f2mul(hg, x0));
        x1 = f2fma(rr, c01, f2mul(hg, x1));
        x2 = f2fma(rr, c02, f2mul(hg, x2));
        x3 = f2fma(rr, c10, f2mul(hg, x3));
        x4 = f2fma(rr, c11, f2mul(hg, x4));
        x5 = f2fma(rr, c12, f2mul(hg, x5));
        x6 = f2fma(rr, c20, f2mul(hg, x6));
        x7 = f2fma(rr, c21, f2mul(hg, x7));
        x8 = f2fma(rr, c22, f2mul(hg, x8));

        // convergence: ||X||_F^2 -> 3 in both lanes
        u64 fro = f2mul(x0, x0);
        fro = f2fma(x1, x1, fro); fro = f2fma(x2, x2, fro);
        fro = f2fma(x3, x3, fro); fro = f2fma(x4, x4, fro);
        fro = f2fma(x5, x5, fro); fro = f2fma(x6, x6, fro);
        fro = f2fma(x7, x7, fro); fro = f2fma(x8, x8, fro);
        float fl, fh;
        f2unpack(fro, fl, fh);
        const bool ok = (fabsf(fl - 3.0f) < 2e-5f) && (fabsf(fh - 3.0f) < 2e-5f);
        if (__all_sync(0xffffffffu, ok)) break;
    }

    // ---- stage to smem, cooperative vectorized store ----
    {
        const int olo = 2 * tid * 9, ohi = olo + 9;
        float a, b;
        f2unpack(x0, a, b); s[olo + 0] = a; s[ohi + 0] = b;
        f2unpack(x1, a, b); s[olo + 1] = a; s[ohi + 1] = b;
        f2unpack(x2, a, b); s[olo + 2] = a; s[ohi + 2] = b;
        f2unpack(x3, a, b); s[olo + 3] = a; s[ohi + 3] = b;
        f2unpack(x4, a, b); s[olo + 4] = a; s[ohi + 4] = b;
        f2unpack(x5, a, b); s[olo + 5] = a; s[ohi + 5] = b;
        f2unpack(x6, a, b); s[olo + 6] = a; s[ohi + 6] = b;
        f2unpack(x7, a, b); s[olo + 7] = a; s[ohi + 7] = b;
        f2unpack(x8, a, b); s[olo + 8] = a; s[ohi + 8] = b;
    }
    __syncthreads();
    {
        float* g = out + (size_t)base * 9;
        const int nv = nflt >> 2;
        const float4* s4 = reinterpret_cast<const float4*>(s);
        float4* g4 = reinterpret_cast<float4*>(g);
        for (int i = tid; i < nv; i += TPB) g4[i] = s4[i];
        for (int i = (nv << 2) + tid; i < nflt; i += TPB) g[i] = s[i];
    }

    for (int i = tid; i < nmat; i += TPB) logdet[base + i] = 0.0f;
}

__global__ void zero_tail_kernel(float* __restrict__ p, long long n)
{
    long long i = (long long)blockIdx.x * blockDim.x + threadIdx.x;
    if (i < n) p[i] = 0.0f;
}

extern "C" void kernel_launch(void* const* d_in, const int* in_sizes, int n_in,
                              void* d_out, int out_size)
{
    const float* rot = (const float*)d_in[0];
    const float* mat = (const float*)d_in[1];
    float* out = (float*)d_out;

    const int N = in_sizes[0] / 9;
    float* logdet = out + (size_t)N * 9;

    const int mats_per_block = TPB * 2;
    const int blocks = (N + mats_per_block - 1) / mats_per_block;
    polar2_kernel<<<blocks, TPB>>>(rot, mat, out, logdet, N);

    const long long used = 10LL * N;
    if ((long long)out_size > used) {
        const long long extra = (long long)out_size - used;
        const int zb = (int)((extra + 255) / 256);
        zero_tail_kernel<<<zb, 256>>>(out + used, extra);
    }
}

// round 3
// speedup vs baseline: 1.3926x; 1.1242x over previous
#include <cuda_runtime.h>

// Polar decomposition of A = rotation[n] @ mat, 2 matrices per thread packed
// into f32x2 (Blackwell FFMA2). Det-scaled Newton:
//   X <- 0.5*g*X + 0.5*g^2*sign(det)*cof(X),   g = |det X|^(-1/3)
// (uses det(gX) = sign(det) exactly, so no reciprocal is needed)

#define TPB 256
typedef unsigned long long u64;

__device__ __forceinline__ u64 f2pack(float lo, float hi) {
    u64 r; asm("mov.b64 %0, {%1, %2};" : "=l"(r) : "f"(lo), "f"(hi)); return r;
}
__device__ __forceinline__ void f2unpack(u64 v, float& lo, float& hi) {
    asm("mov.b64 {%0, %1}, %2;" : "=f"(lo), "=f"(hi) : "l"(v));
}
__device__ __forceinline__ u64 f2mul(u64 a, u64 b) {
    u64 d; asm("mul.rn.f32x2 %0, %1, %2;" : "=l"(d) : "l"(a), "l"(b)); return d;
}
__device__ __forceinline__ u64 f2fma(u64 a, u64 b, u64 c) {
    u64 d; asm("fma.rn.f32x2 %0, %1, %2, %3;" : "=l"(d) : "l"(a), "l"(b), "l"(c)); return d;
}
__device__ __forceinline__ u64 f2neg(u64 a) { return a ^ 0x8000000080000000ULL; }
__device__ __forceinline__ u64 f2msub(u64 a, u64 b, u64 c, u64 d) {
    return f2fma(a, b, f2neg(f2mul(c, d)));
}
__device__ __forceinline__ float lg2_fast(float x) {
    float r; asm("lg2.approx.f32 %0, %1;" : "=f"(r) : "f"(x)); return r;
}
__device__ __forceinline__ float ex2_fast(float x) {
    float r; asm("ex2.approx.f32 %0, %1;" : "=f"(r) : "f"(x)); return r;
}

struct P2 { u64 x0,x1,x2,x3,x4,x5,x6,x7,x8; };

// One det-scaled Newton step (rcp-free).
__device__ __forceinline__ void newton_step(P2& X) {
    const u64 c00 = f2msub(X.x4, X.x8, X.x5, X.x7);
    const u64 c01 = f2msub(X.x5, X.x6, X.x3, X.x8);
    const u64 c02 = f2msub(X.x3, X.x7, X.x4, X.x6);
    const u64 c10 = f2msub(X.x2, X.x7, X.x1, X.x8);
    const u64 c11 = f2msub(X.x0, X.x8, X.x2, X.x6);
    const u64 c12 = f2msub(X.x1, X.x6, X.x0, X.x7);
    const u64 c20 = f2msub(X.x1, X.x5, X.x2, X.x4);
    const u64 c21 = f2msub(X.x2, X.x3, X.x0, X.x5);
    const u64 c22 = f2msub(X.x0, X.x4, X.x1, X.x3);
    const u64 det = f2fma(X.x0, c00, f2fma(X.x1, c01, f2mul(X.x2, c02)));

    float dl, dh;
    f2unpack(det, dl, dh);
    const float gl = ex2_fast(-0.33333333f * lg2_fast(fmaxf(fabsf(dl), 1e-36f)));
    const float gh = ex2_fast(-0.33333333f * lg2_fast(fmaxf(fabsf(dh), 1e-36f)));
    // 0.5/(g*det) == 0.5*g^2*sign(det) exactly, since |g^3*det| == 1
    const float rl = copysignf(0.5f * gl * gl, dl);
    const float rh = copysignf(0.5f * gh * gh, dh);
    const u64 hg = f2pack(0.5f * gl, 0.5f * gh);
    const u64 rr = f2pack(rl, rh);

    X.x0 = f2fma(rr, c00, f2mul(hg, X.x0));
    X.x1 = f2fma(rr, c01, f2mul(hg, X.x1));
    X.x2 = f2fma(rr, c02, f2mul(hg, X.x2));
    X.x3 = f2fma(rr, c10, f2mul(hg, X.x3));
    X.x4 = f2fma(rr, c11, f2mul(hg, X.x4));
    X.x5 = f2fma(rr, c12, f2mul(hg, X.x5));
    X.x6 = f2fma(rr, c20, f2mul(hg, X.x6));
    X.x7 = f2fma(rr, c21, f2mul(hg, X.x7));
    X.x8 = f2fma(rr, c22, f2mul(hg, X.x8));
}

__global__ void __launch_bounds__(TPB)
polar2_kernel(const float* __restrict__ rot,
              const float* __restrict__ mat,
              float* __restrict__ out,
              float* __restrict__ logdet,
              int N)
{
    __shared__ float s[TPB * 18];
    const int tid  = threadIdx.x;
    const int base = blockIdx.x * (TPB * 2);
    const int nmat = min(TPB * 2, N - base);
    const int nflt = nmat * 9;

    // ---- cooperative vectorized load: global -> smem ----
    {
        const float* g = rot + (size_t)base * 9;
        const int nv = nflt >> 2;
        const float4* g4 = reinterpret_cast<const float4*>(g);
        float4* s4 = reinterpret_cast<float4*>(s);
        for (int i = tid; i < nv; i += TPB) s4[i] = g4[i];
        for (int i = (nv << 2) + tid; i < nflt; i += TPB) s[i] = g[i];
    }

    const float m0 = __ldg(mat + 0), m1 = __ldg(mat + 1), m2 = __ldg(mat + 2);
    const float m3 = __ldg(mat + 3), m4 = __ldg(mat + 4), m5 = __ldg(mat + 5);
    const float m6 = __ldg(mat + 6), m7 = __ldg(mat + 7), m8 = __ldg(mat + 8);
    __syncthreads();

    const bool vlo = (base + 2 * tid)     < N;
    const bool vhi = (base + 2 * tid + 1) < N;

    u64 R[9];
    {
        const int olo = 2 * tid * 9, ohi = olo + 9;
        #pragma unroll
        for (int k = 0; k < 9; ++k) {
            const float idv = (k == 0 || k == 4 || k == 8) ? 1.0f : 0.0f;
            const float a = vlo ? s[olo + k] : idv;
            const float b = vhi ? s[ohi + k] : idv;
            R[k] = f2pack(a, b);
        }
    }
    __syncthreads();

    const u64 M0 = f2pack(m0, m0), M1 = f2pack(m1, m1), M2 = f2pack(m2, m2);
    const u64 M3 = f2pack(m3, m3), M4 = f2pack(m4, m4), M5 = f2pack(m5, m5);
    const u64 M6 = f2pack(m6, m6), M7 = f2pack(m7, m7), M8 = f2pack(m8, m8);

    P2 X;
    X.x0 = f2fma(R[0], M0, f2fma(R[1], M3, f2mul(R[2], M6)));
    X.x1 = f2fma(R[0], M1, f2fma(R[1], M4, f2mul(R[2], M7)));
    X.x2 = f2fma(R[0], M2, f2fma(R[1], M5, f2mul(R[2], M8)));
    X.x3 = f2fma(R[3], M0, f2fma(R[4], M3, f2mul(R[5], M6)));
    X.x4 = f2fma(R[3], M1, f2fma(R[4], M4, f2mul(R[5], M7)));
    X.x5 = f2fma(R[3], M2, f2fma(R[4], M5, f2mul(R[5], M8)));
    X.x6 = f2fma(R[6], M0, f2fma(R[7], M3, f2mul(R[8], M6)));
    X.x7 = f2fma(R[6], M1, f2fma(R[7], M4, f2mul(R[8], M7)));
    X.x8 = f2fma(R[6], M2, f2fma(R[7], M5, f2mul(R[8], M8)));

    // ---- 4 unrolled iterations, no convergence check ----
    #pragma unroll
    for (int it = 0; it < 4; ++it) newton_step(X);

    // ---- adaptive tail with warp-uniform early exit ----
    #pragma unroll 1
    for (int it = 0; it < 8; ++it) {
        // ||X||_F^2 -> 3 from above; element error ~ |fro-3|/2
        u64 fro = f2mul(X.x0, X.x0);
        fro = f2fma(X.x1, X.x1, fro); fro = f2fma(X.x2, X.x2, fro);
        fro = f2fma(X.x3, X.x3, fro); fro = f2fma(X.x4, X.x4, fro);
        fro = f2fma(X.x5, X.x5, fro); fro = f2fma(X.x6, X.x6, fro);
        fro = f2fma(X.x7, X.x7, fro); fro = f2fma(X.x8, X.x8, fro);
        float fl, fh;
        f2unpack(fro, fl, fh);
        const bool ok = (fabsf(fl - 3.0f) < 2.5e-4f) && (fabsf(fh - 3.0f) < 2.5e-4f);
        if (__all_sync(0xffffffffu, ok)) break;
        newton_step(X);
    }

    // ---- stage to smem, cooperative vectorized store ----
    {
        const int olo = 2 * tid * 9, ohi = olo + 9;
        float a, b;
        f2unpack(X.x0, a, b); s[olo + 0] = a; s[ohi + 0] = b;
        f2unpack(X.x1, a, b); s[olo + 1] = a; s[ohi + 1] = b;
        f2unpack(X.x2, a, b); s[olo + 2] = a; s[ohi + 2] = b;
        f2unpack(X.x3, a, b); s[olo + 3] = a; s[ohi + 3] = b;
        f2unpack(X.x4, a, b); s[olo + 4] = a; s[ohi + 4] = b;
        f2unpack(X.x5, a, b); s[olo + 5] = a; s[ohi + 5] = b;
        f2unpack(X.x6, a, b); s[olo + 6] = a; s[ohi + 6] = b;
        f2unpack(X.x7, a, b); s[olo + 7] = a; s[ohi + 7] = b;
        f2unpack(X.x8, a, b); s[olo + 8] = a; s[ohi + 8] = b;
    }
    __syncthreads();
    {
        float* g = out + (size_t)base * 9;
        const int nv = nflt >> 2;
        const float4* s4 = reinterpret_cast<const float4*>(s);
        float4* g4 = reinterpret_cast<float4*>(g);
        for (int i = tid; i < nv; i += TPB) g4[i] = s4[i];
        for (int i = (nv << 2) + tid; i < nflt; i += TPB) g[i] = s[i];
    }

    for (int i = tid; i < nmat; i += TPB) logdet[base + i] = 0.0f;
}

__global__ void zero_tail_kernel(float* __restrict__ p, long long n)
{
    long long i = (long long)blockIdx.x * blockDim.x + threadIdx.x;
    if (i < n) p[i] = 0.0f;
}

extern "C" void kernel_launch(void* const* d_in, const int* in_sizes, int n_in,
                              void* d_out, int out_size)
{
    const float* rot = (const float*)d_in[0];
    const float* mat = (const float*)d_in[1];
    float* out = (float*)d_out;

    const int N = in_sizes[0] / 9;
    float* logdet = out + (size_t)N * 9;

    const int mats_per_block = TPB * 2;
    const int blocks = (N + mats_per_block - 1) / mats_per_block;
    polar2_kernel<<<blocks, TPB>>>(rot, mat, out, logdet, N);

    const long long used = 10LL * N;
    if ((long long)out_size > used) {
        const long long extra = (long long)out_size - used;
        const int zb = (int)((extra + 255) / 256);
        zero_tail_kernel<<<zb, 256>>>(out + used, extra);
    }
}